// round 10
// baseline (speedup 1.0000x reference)
#include <cuda_runtime.h>

// Problem constants (shapes fixed by the dataset)
#define NMAX   100000
#define EMAX   3200000
#define F_INC  256
#define HIDC   16
#define CLSC   16
#define KST    2
#define JW     (KST*HIDC)   // 32 = fused K*HID width for layer-1 tensors

// ---------------- device scratch (no allocations allowed) ----------------
__device__ int   g_is64;
__device__ __align__(16) float g_deg [NMAX];
__device__ __align__(16) float g_dinv[NMAX];
__device__ __align__(16) int   g_src [EMAX];
__device__ __align__(16) int   g_dst [EMAX];
__device__ __align__(16) float g_norm[EMAX];
__device__ __align__(16) float g_h1  [NMAX * JW];   // x @ init_w1  (both stacks)
__device__ __align__(16) float g_r1  [NMAX * JW];   // x @ root_w1
__device__ __align__(16) float g_agg1[NMAX * JW];
__device__ __align__(16) float g_hf  [NMAX * HIDC]; // relu-mean feature h [N,16]
__device__ __align__(16) float g_aggh[NMAX * HIDC]; // S @ h  [N,16]

// ---------------- f32x2 packed-FMA helpers (Blackwell) ----------------
__device__ __forceinline__ unsigned long long pk2(float x) {
    unsigned long long r;
    asm("mov.b64 %0, {%1,%2};" : "=l"(r) : "f"(x), "f"(x));
    return r;
}
__device__ __forceinline__ void ffma2(unsigned long long& d,
                                      unsigned long long a,
                                      unsigned long long b) {
    asm("fma.rn.f32x2 %0, %1, %2, %0;" : "+l"(d) : "l"(a), "l"(b));
}

// ---------------- dtype detector: int64 vs int32 edge_index ----------------
__global__ void detect_kernel(const unsigned int* __restrict__ ei) {
    if (blockIdx.x == 0 && threadIdx.x == 0) {
        int nz = 0;
        for (int i = 1; i < 2048; i += 2) nz += (ei[i] != 0u);
        g_is64 = (nz == 0) ? 1 : 0;
    }
}

__device__ __forceinline__ int load_idx(const void* ei, long long i) {
    if (g_is64) return (int)((const long long*)ei)[i];
    return ((const int*)ei)[i];
}

// ---------------- zero scratch accumulators ----------------
__global__ void zero_kernel(int N) {
    int stride = gridDim.x * blockDim.x;
    int i0 = blockIdx.x * blockDim.x + threadIdx.x;
    for (int k = i0; k < N; k += stride) g_deg[k] = 0.f;
    int t32 = N * JW;
    for (int k = i0; k < t32; k += stride) g_agg1[k] = 0.f;
    int t16 = N * HIDC;
    for (int k = i0; k < t16; k += stride) g_aggh[k] = 0.f;
}

// ---------------- degree (from dst / col index, matching gcn_norm) --------
__global__ void deg_kernel(const void* __restrict__ ei, int E) {
    int e = blockIdx.x * blockDim.x + threadIdx.x;
    if (e >= E) return;
    int d = load_idx(ei, (long long)E + e);
    atomicAdd(&g_deg[d], 1.0f);
}

__global__ void dinv_kernel(int N) {
    int n = blockIdx.x * blockDim.x + threadIdx.x;
    if (n >= N) return;
    float dg = g_deg[n];
    g_dinv[n] = (dg > 0.f) ? rsqrtf(dg) : 0.f;
}

// ---------------- edge prep: decode indices once, compute norm ------------
__global__ void prep_kernel(const void* __restrict__ ei, int E) {
    int e = blockIdx.x * blockDim.x + threadIdx.x;
    if (e >= E) return;
    int s = load_idx(ei, e);
    int d = load_idx(ei, (long long)E + e);
    g_src[e] = s;
    g_dst[e] = d;
    g_norm[e] = g_dinv[s] * g_dinv[d];
}

// ---------------- GEMM1: h1 = x @ init_w1, r1 = x @ root_w1 (fused, 64 outs)
// Block: 256 threads, 64 nodes. Thread (nid=t/4, jq=t%4) computes 16 outputs
// as 8 packed f32x2 accumulators. Weight LDS order is xor-rotated by jq so
// the four LDS.128 per fl are bank-conflict-free across lanes.
__global__ __launch_bounds__(256) void gemm1_kernel(
    const float* __restrict__ x,
    const float* __restrict__ iw,   // [K, F_IN, HID]
    const float* __restrict__ rw,   // [K, F_IN, HID]
    int N)
{
    __shared__ __align__(16) float xs[64][65];    // padded: conflict-free
    __shared__ __align__(16) float ws[64][64];    // ws[fl][j]: j<32 init, j>=32 root

    int t   = threadIdx.x;
    int n0  = blockIdx.x * 64;
    int nid = t >> 2;
    int jq  = t & 3;
    int n   = n0 + nid;

    unsigned long long acc[8];
    #pragma unroll
    for (int o = 0; o < 8; o++) acc[o] = 0ull;   // bit pattern {0.f, 0.f}

    for (int f0 = 0; f0 < F_INC; f0 += 64) {
        // load x tile: 64 nodes x 64 features (coalesced float4)
        #pragma unroll
        for (int i = 0; i < 4; i++) {
            int idx = t + i * 256;          // 0..1023 float4 slots
            int nn  = idx >> 4;
            int fq  = idx & 15;
            float4 v = make_float4(0.f, 0.f, 0.f, 0.f);
            if (n0 + nn < N)
                v = *(const float4*)&x[(long long)(n0 + nn) * F_INC + f0 + fq * 4];
            xs[nn][fq * 4 + 0] = v.x;
            xs[nn][fq * 4 + 1] = v.y;
            xs[nn][fq * 4 + 2] = v.z;
            xs[nn][fq * 4 + 3] = v.w;
        }
        // load weight tile: 64 f x 64 j
        #pragma unroll
        for (int i = 0; i < 16; i++) {
            int idx = t + i * 256;          // 0..4095
            int fl  = idx >> 6;
            int j   = idx & 63;
            float v;
            if (j < 32)
                v = iw[(j >> 4) * (F_INC * HIDC) + (f0 + fl) * HIDC + (j & 15)];
            else {
                int jj = j - 32;
                v = rw[(jj >> 4) * (F_INC * HIDC) + (f0 + fl) * HIDC + (jj & 15)];
            }
            ws[fl][j] = v;
        }
        __syncthreads();

        #pragma unroll 8
        for (int fl = 0; fl < 64; fl++) {
            float xv = xs[nid][fl];
            unsigned long long xd = pk2(xv);
            #pragma unroll
            for (int m = 0; m < 4; m++) {
                int i = (m + jq) & 3;       // xor-rotated: conflict-free LDS.128
                ulonglong2 wv = *(const ulonglong2*)&ws[fl][jq * 16 + i * 4];
                ffma2(acc[2 * i + 0], xd, wv.x);
                ffma2(acc[2 * i + 1], xd, wv.y);
            }
        }
        __syncthreads();
    }

    if (n < N) {
        float* base = (jq < 2) ? &g_h1[n * JW + jq * 16]
                               : &g_r1[n * JW + (jq - 2) * 16];
        ulonglong2* d2 = (ulonglong2*)base;
        d2[0] = make_ulonglong2(acc[0], acc[1]);
        d2[1] = make_ulonglong2(acc[2], acc[3]);
        d2[2] = make_ulonglong2(acc[4], acc[5]);
        d2[3] = make_ulonglong2(acc[6], acc[7]);
    }
}

// ---------------- edge scatter: agg[dst] += h[src] * norm ------------------
// WIDTH/4 lanes per edge; each lane does one LDG.128 gather + one RED.128
// (red.global.add.v4.f32, sm_90+). 4x fewer lane-ops than scalar atomics.
#define EPW 4
template<int WIDTH, int PASS>
__global__ __launch_bounds__(256) void scatter_v4(int E) {
    const float* __restrict__ h = PASS ? g_hf : g_h1;
    float* agg = PASS ? g_aggh : g_agg1;
    constexpr int LPE = WIDTH / 4;       // lanes per edge
    constexpr int EPWARP = 32 / LPE;     // edges per warp per step

    int gid  = blockIdx.x * blockDim.x + threadIdx.x;
    int warp = gid >> 5;
    int lane = gid & 31;
    int q  = lane % LPE;
    int eo = lane / LPE;
    int e0 = warp * (EPWARP * EPW);
    #pragma unroll
    for (int i = 0; i < EPW; i++) {
        int e = e0 + i * EPWARP + eo;
        if (e < E) {
            int   s = g_src[e];
            int   d = g_dst[e];
            float w = g_norm[e];
            float4 hv = *(const float4*)&h[s * WIDTH + q * 4];
            float* p = &agg[d * WIDTH + q * 4];
            asm volatile("red.global.add.v4.f32 [%0], {%1,%2,%3,%4};"
                         :: "l"(p), "f"(hv.x * w), "f"(hv.y * w),
                            "f"(hv.z * w), "f"(hv.w * w) : "memory");
        }
    }
}

// ---------------- combine conv1: h = mean_k relu(agg + root + bias) --------
__global__ __launch_bounds__(256) void combine_kernel(
    const float* __restrict__ b1,    // [K, HID] = 32
    float* __restrict__ feat_out,
    int N, int write_feat)
{
    __shared__ float b1s[32];
    int t = threadIdx.x;
    if (t < 32) b1s[t] = b1[t];
    __syncthreads();

    int n = blockIdx.x * blockDim.x + t;
    if (n >= N) return;

    float pre[32];
    const float4* a4 = (const float4*)&g_agg1[n * JW];
    const float4* r4 = (const float4*)&g_r1 [n * JW];
    #pragma unroll
    for (int q = 0; q < 8; q++) {
        float4 av = a4[q], rv = r4[q];
        pre[q * 4 + 0] = av.x + rv.x + b1s[q * 4 + 0];
        pre[q * 4 + 1] = av.y + rv.y + b1s[q * 4 + 1];
        pre[q * 4 + 2] = av.z + rv.z + b1s[q * 4 + 2];
        pre[q * 4 + 3] = av.w + rv.w + b1s[q * 4 + 3];
    }
    float h[16];
    #pragma unroll
    for (int o = 0; o < 16; o++) {
        float a0 = fmaxf(pre[o],      0.f);
        float a1 = fmaxf(pre[16 + o], 0.f);
        h[o] = 0.5f * (a0 + a1);   // mean over K; outer relu is a no-op (>=0)
    }
    float4* hf4 = (float4*)&g_hf[n * HIDC];
    float4 v0 = make_float4(h[0],  h[1],  h[2],  h[3]);
    float4 v1 = make_float4(h[4],  h[5],  h[6],  h[7]);
    float4 v2 = make_float4(h[8],  h[9],  h[10], h[11]);
    float4 v3 = make_float4(h[12], h[13], h[14], h[15]);
    hf4[0] = v0; hf4[1] = v1; hf4[2] = v2; hf4[3] = v3;
    if (write_feat) {
        float4* f4 = (float4*)&feat_out[(long long)n * CLSC];
        f4[0] = v0; f4[1] = v1; f4[2] = v2; f4[3] = v3;
    }
}

// ---------------- final: logits = (S@h)@Wi + h@Wr + b, then log_softmax ----
// Layer-2 is linear per stack and the stack-mean is linear, so both stacks
// fold into pre-summed 16x16 weights (exact algebra, just re-associated).
__global__ __launch_bounds__(256) void final_kernel(
    const float* __restrict__ iw2,   // [K, HID, C]
    const float* __restrict__ rw2,   // [K, HID, C]
    const float* __restrict__ b2,    // [K, C]
    float* __restrict__ out, int N)
{
    __shared__ float wi[16][16], wr[16][16], bs[16];
    int t = threadIdx.x;
    {
        int o = t >> 4, c = t & 15;
        wi[o][c] = 0.5f * (iw2[o * 16 + c] + iw2[256 + o * 16 + c]);
        wr[o][c] = 0.5f * (rw2[o * 16 + c] + rw2[256 + o * 16 + c]);
    }
    if (t < 16) bs[t] = 0.5f * (b2[t] + b2[16 + t]);
    __syncthreads();

    int n = blockIdx.x * blockDim.x + t;
    if (n >= N) return;

    float ah[16], hh[16];
    const float4* a4 = (const float4*)&g_aggh[n * HIDC];
    const float4* h4 = (const float4*)&g_hf [n * HIDC];
    #pragma unroll
    for (int q = 0; q < 4; q++) {
        float4 av = a4[q], hv = h4[q];
        ah[q * 4 + 0] = av.x; ah[q * 4 + 1] = av.y;
        ah[q * 4 + 2] = av.z; ah[q * 4 + 3] = av.w;
        hh[q * 4 + 0] = hv.x; hh[q * 4 + 1] = hv.y;
        hh[q * 4 + 2] = hv.z; hh[q * 4 + 3] = hv.w;
    }
    float lg[16];
    #pragma unroll
    for (int c = 0; c < 16; c++) lg[c] = bs[c];
    #pragma unroll
    for (int o = 0; o < 16; o++) {
        float a = ah[o], h = hh[o];
        #pragma unroll
        for (int c = 0; c < 16; c++)
            lg[c] = fmaf(a, wi[o][c], fmaf(h, wr[o][c], lg[c]));
    }
    float m = -1e30f;
    #pragma unroll
    for (int c = 0; c < 16; c++) m = fmaxf(m, lg[c]);
    float s = 0.f;
    #pragma unroll
    for (int c = 0; c < 16; c++) s += __expf(lg[c] - m);
    float lse = m + __logf(s);

    float4* o4 = (float4*)&out[(long long)n * CLSC];
    o4[0] = make_float4(lg[0] - lse,  lg[1] - lse,  lg[2] - lse,  lg[3] - lse);
    o4[1] = make_float4(lg[4] - lse,  lg[5] - lse,  lg[6] - lse,  lg[7] - lse);
    o4[2] = make_float4(lg[8] - lse,  lg[9] - lse,  lg[10] - lse, lg[11] - lse);
    o4[3] = make_float4(lg[12] - lse, lg[13] - lse, lg[14] - lse, lg[15] - lse);
}

// ---------------- launch ----------------
extern "C" void kernel_launch(void* const* d_in, const int* in_sizes, int n_in,
                              void* d_out, int out_size) {
    const float* x   = (const float*)d_in[0];
    const void*  ei  = d_in[1];                  // int32 or int64, detected on device
    const float* iw1 = (const float*)d_in[2];
    const float* rw1 = (const float*)d_in[3];
    const float* b1  = (const float*)d_in[4];
    const float* iw2 = (const float*)d_in[5];
    const float* rw2 = (const float*)d_in[6];
    const float* b2  = (const float*)d_in[7];
    float* out = (float*)d_out;

    int N = in_sizes[0] / F_INC;
    int E = in_sizes[1] / 2;
    if (N > NMAX) N = NMAX;
    if (E > EMAX) E = EMAX;

    int write_feat = (out_size >= 2 * N * CLSC) ? 1 : 0;
    float* feat_out = write_feat ? (out + (long long)N * CLSC) : out;

    detect_kernel<<<1, 32>>>((const unsigned int*)ei);
    zero_kernel<<<2048, 256>>>(N);
    deg_kernel<<<(E + 255) / 256, 256>>>(ei, E);
    dinv_kernel<<<(N + 255) / 256, 256>>>(N);
    prep_kernel<<<(E + 255) / 256, 256>>>(ei, E);
    gemm1_kernel<<<(N + 63) / 64, 256>>>(x, iw1, rw1, N);

    // pass 1: width 32 -> 128 edges per block
    scatter_v4<32, 0><<<(E + 127) / 128, 256>>>(E);

    combine_kernel<<<(N + 255) / 256, 256>>>(b1, feat_out, N, write_feat);

    // pass 2: width 16 -> 256 edges per block
    scatter_v4<16, 1><<<(E + 255) / 256, 256>>>(E);

    final_kernel<<<(N + 255) / 256, 256>>>(iw2, rw2, b2, out, N);
}

// round 11
// speedup vs baseline: 8.2708x; 8.2708x over previous
#include <cuda_runtime.h>

// Problem constants (shapes fixed by the dataset)
#define NMAX   100000
#define EMAX   3200000
#define F_INC  256
#define HIDC   16
#define CLSC   16
#define KST    2
#define JW     (KST*HIDC)   // 32 = fused K*HID width for layer-1 tensors

// ---------------- device scratch (no allocations allowed) ----------------
__device__ int   g_is64;
__device__ __align__(16) float g_deg [NMAX];
__device__ __align__(16) float g_dinv[NMAX];
__device__ __align__(16) int   g_src [EMAX];
__device__ __align__(16) int   g_dst [EMAX];
__device__ __align__(16) float g_norm[EMAX];
__device__ __align__(16) float g_h1  [NMAX * JW];   // x @ init_w1  (both stacks)
__device__ __align__(16) float g_r1  [NMAX * JW];   // x @ root_w1
__device__ __align__(16) float g_agg1[NMAX * JW];
__device__ __align__(16) float g_hf  [NMAX * HIDC]; // relu-mean feature h [N,16]
__device__ __align__(16) float g_aggh[NMAX * HIDC]; // S @ h  [N,16]

// ---------------- dtype detector: int64 vs int32 edge_index ----------------
// Node ids < 100000. If little-endian int64, every odd 32-bit word is 0.
__global__ void detect_kernel(const unsigned int* __restrict__ ei) {
    if (blockIdx.x == 0 && threadIdx.x == 0) {
        int nz = 0;
        for (int i = 1; i < 2048; i += 2) nz += (ei[i] != 0u);
        g_is64 = (nz == 0) ? 1 : 0;
    }
}

__device__ __forceinline__ int load_idx(const void* ei, long long i) {
    if (g_is64) return (int)((const long long*)ei)[i];
    return ((const int*)ei)[i];
}

// ---------------- zero scratch accumulators ----------------
__global__ void zero_kernel(int N) {
    int stride = gridDim.x * blockDim.x;
    int i0 = blockIdx.x * blockDim.x + threadIdx.x;
    for (int k = i0; k < N; k += stride) g_deg[k] = 0.f;
    int t32 = N * JW;
    for (int k = i0; k < t32; k += stride) g_agg1[k] = 0.f;
    int t16 = N * HIDC;
    for (int k = i0; k < t16; k += stride) g_aggh[k] = 0.f;
}

// ---------------- degree (from dst / col index, matching gcn_norm) --------
__global__ void deg_kernel(const void* __restrict__ ei, int E) {
    int e = blockIdx.x * blockDim.x + threadIdx.x;
    if (e >= E) return;
    int d = load_idx(ei, (long long)E + e);
    atomicAdd(&g_deg[d], 1.0f);
}

__global__ void dinv_kernel(int N) {
    int n = blockIdx.x * blockDim.x + threadIdx.x;
    if (n >= N) return;
    float dg = g_deg[n];
    g_dinv[n] = (dg > 0.f) ? rsqrtf(dg) : 0.f;
}

// ---------------- edge prep: decode indices once, compute norm ------------
__global__ void prep_kernel(const void* __restrict__ ei, int E) {
    int e = blockIdx.x * blockDim.x + threadIdx.x;
    if (e >= E) return;
    int s = load_idx(ei, e);
    int d = load_idx(ei, (long long)E + e);
    g_src[e] = s;
    g_dst[e] = d;
    g_norm[e] = g_dinv[s] * g_dinv[d];
}

// ---------------- GEMM1: h1 = x @ init_w1, r1 = x @ root_w1 (fused, 64 outs)
// Block: 256 threads, 64 nodes. Thread (nid = t/4, jq = t%4) computes 16 outputs.
// (R9-proven scalar-FFMA version.)
__global__ __launch_bounds__(256) void gemm1_kernel(
    const float* __restrict__ x,
    const float* __restrict__ iw,   // [K, F_IN, HID]
    const float* __restrict__ rw,   // [K, F_IN, HID]
    int N)
{
    __shared__ float xs[64][65];    // padded: conflict-free
    __shared__ float ws[64][64];    // ws[fl][j]: j<32 init, j>=32 root

    int t   = threadIdx.x;
    int n0  = blockIdx.x * 64;
    int nid = t >> 2;
    int jq  = t & 3;
    int n   = n0 + nid;

    float acc[16];
    #pragma unroll
    for (int o = 0; o < 16; o++) acc[o] = 0.f;

    for (int f0 = 0; f0 < F_INC; f0 += 64) {
        // load x tile: 64 nodes x 64 features (coalesced float4)
        #pragma unroll
        for (int i = 0; i < 4; i++) {
            int idx = t + i * 256;          // 0..1023 float4 slots
            int nn  = idx >> 4;
            int fq  = idx & 15;
            float4 v = make_float4(0.f, 0.f, 0.f, 0.f);
            if (n0 + nn < N)
                v = *(const float4*)&x[(long long)(n0 + nn) * F_INC + f0 + fq * 4];
            xs[nn][fq * 4 + 0] = v.x;
            xs[nn][fq * 4 + 1] = v.y;
            xs[nn][fq * 4 + 2] = v.z;
            xs[nn][fq * 4 + 3] = v.w;
        }
        // load weight tile: 64 f x 64 j
        #pragma unroll
        for (int i = 0; i < 16; i++) {
            int idx = t + i * 256;          // 0..4095
            int fl  = idx >> 6;
            int j   = idx & 63;
            float v;
            if (j < 32)
                v = iw[(j >> 4) * (F_INC * HIDC) + (f0 + fl) * HIDC + (j & 15)];
            else {
                int jj = j - 32;
                v = rw[(jj >> 4) * (F_INC * HIDC) + (f0 + fl) * HIDC + (jj & 15)];
            }
            ws[fl][j] = v;
        }
        __syncthreads();

        #pragma unroll 8
        for (int fl = 0; fl < 64; fl++) {
            float xv = xs[nid][fl];
            const float4* w4 = (const float4*)&ws[fl][jq * 16];
            float4 w0 = w4[0], w1 = w4[1], w2 = w4[2], w3 = w4[3];
            acc[0]  = fmaf(xv, w0.x, acc[0]);
            acc[1]  = fmaf(xv, w0.y, acc[1]);
            acc[2]  = fmaf(xv, w0.z, acc[2]);
            acc[3]  = fmaf(xv, w0.w, acc[3]);
            acc[4]  = fmaf(xv, w1.x, acc[4]);
            acc[5]  = fmaf(xv, w1.y, acc[5]);
            acc[6]  = fmaf(xv, w1.z, acc[6]);
            acc[7]  = fmaf(xv, w1.w, acc[7]);
            acc[8]  = fmaf(xv, w2.x, acc[8]);
            acc[9]  = fmaf(xv, w2.y, acc[9]);
            acc[10] = fmaf(xv, w2.z, acc[10]);
            acc[11] = fmaf(xv, w2.w, acc[11]);
            acc[12] = fmaf(xv, w3.x, acc[12]);
            acc[13] = fmaf(xv, w3.y, acc[13]);
            acc[14] = fmaf(xv, w3.z, acc[14]);
            acc[15] = fmaf(xv, w3.w, acc[15]);
        }
        __syncthreads();
    }

    if (n < N) {
        float* base = (jq < 2) ? &g_h1[n * JW + jq * 16]
                               : &g_r1[n * JW + (jq - 2) * 16];
        float4* d4 = (float4*)base;
        d4[0] = make_float4(acc[0],  acc[1],  acc[2],  acc[3]);
        d4[1] = make_float4(acc[4],  acc[5],  acc[6],  acc[7]);
        d4[2] = make_float4(acc[8],  acc[9],  acc[10], acc[11]);
        d4[3] = make_float4(acc[12], acc[13], acc[14], acc[15]);
    }
}

// ---------------- edge scatter: agg[dst] += h[src] * norm ------------------
// WIDTH lanes per edge, scalar LDG.32 + scalar atomicAdd (R9-proven path).
#define EPW 4
template<int WIDTH, int PASS>
__global__ __launch_bounds__(256) void scatter_kernel(int E) {
    const float* __restrict__ h = PASS ? g_hf : g_h1;
    float* agg = PASS ? g_aggh : g_agg1;
    constexpr int EPWARP = 32 / WIDTH;   // edges handled per warp per step

    int gid  = blockIdx.x * blockDim.x + threadIdx.x;
    int warp = gid >> 5;
    int lane = gid & 31;
    int q  = lane % WIDTH;               // feature index
    int eo = lane / WIDTH;               // edge slot within warp
    int e0 = warp * (EPWARP * EPW);
    #pragma unroll
    for (int i = 0; i < EPW; i++) {
        int e = e0 + i * EPWARP + eo;
        if (e < E) {
            int   s = g_src[e];
            int   d = g_dst[e];
            float w = g_norm[e];
            float v = h[s * WIDTH + q] * w;
            atomicAdd(&agg[d * WIDTH + q], v);
        }
    }
}

// ---------------- combine conv1: h = mean_k relu(agg + root + bias) --------
__global__ __launch_bounds__(256) void combine_kernel(
    const float* __restrict__ b1,    // [K, HID] = 32
    float* __restrict__ feat_out,
    int N, int write_feat)
{
    __shared__ float b1s[32];
    int t = threadIdx.x;
    if (t < 32) b1s[t] = b1[t];
    __syncthreads();

    int n = blockIdx.x * blockDim.x + t;
    if (n >= N) return;

    float pre[32];
    const float4* a4 = (const float4*)&g_agg1[n * JW];
    const float4* r4 = (const float4*)&g_r1 [n * JW];
    #pragma unroll
    for (int q = 0; q < 8; q++) {
        float4 av = a4[q], rv = r4[q];
        pre[q * 4 + 0] = av.x + rv.x + b1s[q * 4 + 0];
        pre[q * 4 + 1] = av.y + rv.y + b1s[q * 4 + 1];
        pre[q * 4 + 2] = av.z + rv.z + b1s[q * 4 + 2];
        pre[q * 4 + 3] = av.w + rv.w + b1s[q * 4 + 3];
    }
    float h[16];
    #pragma unroll
    for (int o = 0; o < 16; o++) {
        float a0 = fmaxf(pre[o],      0.f);
        float a1 = fmaxf(pre[16 + o], 0.f);
        h[o] = 0.5f * (a0 + a1);   // mean over K; outer relu is a no-op (>=0)
    }
    float4 v0 = make_float4(h[0],  h[1],  h[2],  h[3]);
    float4 v1 = make_float4(h[4],  h[5],  h[6],  h[7]);
    float4 v2 = make_float4(h[8],  h[9],  h[10], h[11]);
    float4 v3 = make_float4(h[12], h[13], h[14], h[15]);
    float4* hf4 = (float4*)&g_hf[n * HIDC];
    hf4[0] = v0; hf4[1] = v1; hf4[2] = v2; hf4[3] = v3;
    if (write_feat) {
        float4* f4 = (float4*)&feat_out[(long long)n * CLSC];
        f4[0] = v0; f4[1] = v1; f4[2] = v2; f4[3] = v3;
    }
}

// ---------------- final: logits = (S@h)@Wi + h@Wr + b, then log_softmax ----
// Layer-2 is linear per stack and the stack-mean is linear, so both stacks
// fold into pre-summed 16x16 weights (exact re-association of the algebra).
__global__ __launch_bounds__(256) void final_kernel(
    const float* __restrict__ iw2,   // [K, HID, C]
    const float* __restrict__ rw2,   // [K, HID, C]
    const float* __restrict__ b2,    // [K, C]
    float* __restrict__ out, int N)
{
    __shared__ float wi[16][16], wr[16][16], bs[16];
    int t = threadIdx.x;
    {
        int o = t >> 4, c = t & 15;
        wi[o][c] = 0.5f * (iw2[o * 16 + c] + iw2[256 + o * 16 + c]);
        wr[o][c] = 0.5f * (rw2[o * 16 + c] + rw2[256 + o * 16 + c]);
    }
    if (t < 16) bs[t] = 0.5f * (b2[t] + b2[16 + t]);
    __syncthreads();

    int n = blockIdx.x * blockDim.x + t;
    if (n >= N) return;

    float ah[16], hh[16];
    const float4* a4 = (const float4*)&g_aggh[n * HIDC];
    const float4* h4 = (const float4*)&g_hf [n * HIDC];
    #pragma unroll
    for (int q = 0; q < 4; q++) {
        float4 av = a4[q], hv = h4[q];
        ah[q * 4 + 0] = av.x; ah[q * 4 + 1] = av.y;
        ah[q * 4 + 2] = av.z; ah[q * 4 + 3] = av.w;
        hh[q * 4 + 0] = hv.x; hh[q * 4 + 1] = hv.y;
        hh[q * 4 + 2] = hv.z; hh[q * 4 + 3] = hv.w;
    }
    float lg[16];
    #pragma unroll
    for (int c = 0; c < 16; c++) lg[c] = bs[c];
    #pragma unroll
    for (int o = 0; o < 16; o++) {
        float a = ah[o], h = hh[o];
        #pragma unroll
        for (int c = 0; c < 16; c++)
            lg[c] = fmaf(a, wi[o][c], fmaf(h, wr[o][c], lg[c]));
    }
    float m = -1e30f;
    #pragma unroll
    for (int c = 0; c < 16; c++) m = fmaxf(m, lg[c]);
    float s = 0.f;
    #pragma unroll
    for (int c = 0; c < 16; c++) s += __expf(lg[c] - m);
    float lse = m + __logf(s);

    float4* o4 = (float4*)&out[(long long)n * CLSC];
    o4[0] = make_float4(lg[0] - lse,  lg[1] - lse,  lg[2] - lse,  lg[3] - lse);
    o4[1] = make_float4(lg[4] - lse,  lg[5] - lse,  lg[6] - lse,  lg[7] - lse);
    o4[2] = make_float4(lg[8] - lse,  lg[9] - lse,  lg[10] - lse, lg[11] - lse);
    o4[3] = make_float4(lg[12] - lse, lg[13] - lse, lg[14] - lse, lg[15] - lse);
}

// ---------------- launch ----------------
extern "C" void kernel_launch(void* const* d_in, const int* in_sizes, int n_in,
                              void* d_out, int out_size) {
    const float* x   = (const float*)d_in[0];
    const void*  ei  = d_in[1];                  // int32 or int64, detected on device
    const float* iw1 = (const float*)d_in[2];
    const float* rw1 = (const float*)d_in[3];
    const float* b1  = (const float*)d_in[4];
    const float* iw2 = (const float*)d_in[5];
    const float* rw2 = (const float*)d_in[6];
    const float* b2  = (const float*)d_in[7];
    float* out = (float*)d_out;

    int N = in_sizes[0] / F_INC;
    int E = in_sizes[1] / 2;
    if (N > NMAX) N = NMAX;
    if (E > EMAX) E = EMAX;

    int write_feat = (out_size >= 2 * N * CLSC) ? 1 : 0;
    float* feat_out = write_feat ? (out + (long long)N * CLSC) : out;

    detect_kernel<<<1, 32>>>((const unsigned int*)ei);
    zero_kernel<<<2048, 256>>>(N);
    deg_kernel<<<(E + 255) / 256, 256>>>(ei, E);
    dinv_kernel<<<(N + 255) / 256, 256>>>(N);
    prep_kernel<<<(E + 255) / 256, 256>>>(ei, E);
    gemm1_kernel<<<(N + 63) / 64, 256>>>(x, iw1, rw1, N);

    // pass 1: width 32 -> 1 edge/warp/step, EPW=4 -> 32 edges per block
    scatter_kernel<32, 0><<<(E + 31) / 32, 256>>>(E);

    combine_kernel<<<(N + 255) / 256, 256>>>(b1, feat_out, N, write_feat);

    // pass 2: width 16 -> 2 edges/warp/step, EPW=4 -> 64 edges per block
    scatter_kernel<16, 1><<<(E + 63) / 64, 256>>>(E);

    final_kernel<<<(N + 255) / 256, 256>>>(iw2, rw2, b2, out, N);
}

// round 12
// speedup vs baseline: 9.7740x; 1.1818x over previous
#include <cuda_runtime.h>

// Problem constants (shapes fixed by the dataset)
#define NMAX   100000
#define EMAX   3200000
#define F_INC  256
#define HIDC   16
#define CLSC   16
#define KST    2
#define JW     (KST*HIDC)   // 32 = fused K*HID width for layer-1 tensors

// ---------------- device scratch (no allocations allowed) ----------------
__device__ int   g_is64;
__device__ __align__(16) int   g_degi  [NMAX];
__device__ __align__(16) int   g_rowinc[NMAX];      // inclusive scan within block
__device__ __align__(16) int   g_rowptr[NMAX + 1];
__device__ __align__(16) int   g_cur   [NMAX];
__device__ __align__(16) int   g_bsum  [1024];
__device__ __align__(16) int   g_csr   [EMAX];      // src per CSR slot (grouped by dst)
__device__ __align__(16) float g_dinv  [NMAX];
__device__ __align__(16) float g_h1    [NMAX * JW]; // dinv[n] * (x @ init_w1), both stacks
__device__ __align__(16) float g_r1    [NMAX * JW]; // x @ root_w1
__device__ __align__(16) float g_agg1  [NMAX * JW];
__device__ __align__(16) float g_hf    [NMAX * HIDC]; // relu-mean feature h
__device__ __align__(16) float g_hfs   [NMAX * HIDC]; // dinv[n] * h  (scatter operand)
__device__ __align__(16) float g_aggh  [NMAX * HIDC]; // S @ h

// ---------------- dtype detector: int64 vs int32 edge_index ----------------
// Node ids < 100000. If little-endian int64, every odd 32-bit word is 0.
__global__ void detect_kernel(const unsigned int* __restrict__ ei) {
    if (blockIdx.x == 0 && threadIdx.x == 0) {
        int nz = 0;
        for (int i = 1; i < 2048; i += 2) nz += (ei[i] != 0u);
        g_is64 = (nz == 0) ? 1 : 0;
    }
}

__device__ __forceinline__ int load_idx(const void* ei, long long i) {
    if (g_is64) return (int)((const long long*)ei)[i];
    return ((const int*)ei)[i];
}

// ---------------- zero degree counters ----------------
__global__ void zeroi_kernel(int N) {
    int i = blockIdx.x * blockDim.x + threadIdx.x;
    if (i < N) g_degi[i] = 0;
}

// ---------------- degree (from dst / col index, matching gcn_norm) --------
__global__ void deg_kernel(const void* __restrict__ ei, int E) {
    int e = blockIdx.x * blockDim.x + threadIdx.x;
    if (e >= E) return;
    int d = load_idx(ei, (long long)E + e);
    atomicAdd(&g_degi[d], 1);
}

// ---------------- 3-step exclusive scan of degrees -> rowptr --------------
__global__ __launch_bounds__(256) void scan1_kernel(int N) {
    __shared__ int wsum[8];
    int t = threadIdx.x;
    int n = blockIdx.x * 256 + t;
    int v = (n < N) ? g_degi[n] : 0;
    int x = v;
    #pragma unroll
    for (int o = 1; o < 32; o <<= 1) {
        int y = __shfl_up_sync(0xffffffffu, x, o);
        if ((t & 31) >= o) x += y;
    }
    if ((t & 31) == 31) wsum[t >> 5] = x;
    __syncthreads();
    if (t == 0) {
        int run = 0;
        #pragma unroll
        for (int i = 0; i < 8; i++) { int tmp = wsum[i]; wsum[i] = run; run += tmp; }
        g_bsum[blockIdx.x] = run;
    }
    __syncthreads();
    if (n < N) g_rowinc[n] = x + wsum[t >> 5];   // inclusive within block
}

__global__ __launch_bounds__(512) void scan2_kernel(int nb) {
    __shared__ int ws[16];
    int t = threadIdx.x;
    int v = (t < nb) ? g_bsum[t] : 0;
    int x = v;
    #pragma unroll
    for (int o = 1; o < 32; o <<= 1) {
        int y = __shfl_up_sync(0xffffffffu, x, o);
        if ((t & 31) >= o) x += y;
    }
    if ((t & 31) == 31) ws[t >> 5] = x;
    __syncthreads();
    if (t == 0) {
        int run = 0;
        #pragma unroll
        for (int i = 0; i < 16; i++) { int tmp = ws[i]; ws[i] = run; run += tmp; }
    }
    __syncthreads();
    if (t < nb) g_bsum[t] = x + ws[t >> 5] - v;  // exclusive block offsets
}

__global__ __launch_bounds__(256) void scan3_kernel(int N) {
    int n = blockIdx.x * 256 + threadIdx.x;
    if (n >= N) return;
    int d     = g_degi[n];
    int start = g_bsum[blockIdx.x] + g_rowinc[n] - d;
    g_rowptr[n] = start;
    g_cur[n]    = start;
    g_dinv[n]   = (d > 0) ? rsqrtf((float)d) : 0.f;
    if (n == N - 1) g_rowptr[N] = start + d;     // == E
}

// ---------------- CSR fill: csr[pos] = src, grouped by dst ----------------
__global__ void fill_kernel(const void* __restrict__ ei, int E) {
    int e = blockIdx.x * blockDim.x + threadIdx.x;
    if (e >= E) return;
    int s = load_idx(ei, e);
    int d = load_idx(ei, (long long)E + e);
    int pos = atomicAdd(&g_cur[d], 1);
    g_csr[pos] = s;
}

// ---------------- GEMM1: h1 = dinv*(x @ init_w1), r1 = x @ root_w1 --------
// Block: 256 threads, 64 nodes. Thread (nid = t/4, jq = t%4) computes 16 outputs.
__global__ __launch_bounds__(256) void gemm1_kernel(
    const float* __restrict__ x,
    const float* __restrict__ iw,   // [K, F_IN, HID]
    const float* __restrict__ rw,   // [K, F_IN, HID]
    int N)
{
    __shared__ float xs[64][65];    // padded: conflict-free
    __shared__ float ws[64][64];    // ws[fl][j]: j<32 init, j>=32 root

    int t   = threadIdx.x;
    int n0  = blockIdx.x * 64;
    int nid = t >> 2;
    int jq  = t & 3;
    int n   = n0 + nid;

    float acc[16];
    #pragma unroll
    for (int o = 0; o < 16; o++) acc[o] = 0.f;

    for (int f0 = 0; f0 < F_INC; f0 += 64) {
        #pragma unroll
        for (int i = 0; i < 4; i++) {
            int idx = t + i * 256;
            int nn  = idx >> 4;
            int fq  = idx & 15;
            float4 v = make_float4(0.f, 0.f, 0.f, 0.f);
            if (n0 + nn < N)
                v = *(const float4*)&x[(long long)(n0 + nn) * F_INC + f0 + fq * 4];
            xs[nn][fq * 4 + 0] = v.x;
            xs[nn][fq * 4 + 1] = v.y;
            xs[nn][fq * 4 + 2] = v.z;
            xs[nn][fq * 4 + 3] = v.w;
        }
        #pragma unroll
        for (int i = 0; i < 16; i++) {
            int idx = t + i * 256;
            int fl  = idx >> 6;
            int j   = idx & 63;
            float v;
            if (j < 32)
                v = iw[(j >> 4) * (F_INC * HIDC) + (f0 + fl) * HIDC + (j & 15)];
            else {
                int jj = j - 32;
                v = rw[(jj >> 4) * (F_INC * HIDC) + (f0 + fl) * HIDC + (jj & 15)];
            }
            ws[fl][j] = v;
        }
        __syncthreads();

        #pragma unroll 8
        for (int fl = 0; fl < 64; fl++) {
            float xv = xs[nid][fl];
            const float4* w4 = (const float4*)&ws[fl][jq * 16];
            float4 w0 = w4[0], w1 = w4[1], w2 = w4[2], w3 = w4[3];
            acc[0]  = fmaf(xv, w0.x, acc[0]);
            acc[1]  = fmaf(xv, w0.y, acc[1]);
            acc[2]  = fmaf(xv, w0.z, acc[2]);
            acc[3]  = fmaf(xv, w0.w, acc[3]);
            acc[4]  = fmaf(xv, w1.x, acc[4]);
            acc[5]  = fmaf(xv, w1.y, acc[5]);
            acc[6]  = fmaf(xv, w1.z, acc[6]);
            acc[7]  = fmaf(xv, w1.w, acc[7]);
            acc[8]  = fmaf(xv, w2.x, acc[8]);
            acc[9]  = fmaf(xv, w2.y, acc[9]);
            acc[10] = fmaf(xv, w2.z, acc[10]);
            acc[11] = fmaf(xv, w2.w, acc[11]);
            acc[12] = fmaf(xv, w3.x, acc[12]);
            acc[13] = fmaf(xv, w3.y, acc[13]);
            acc[14] = fmaf(xv, w3.z, acc[14]);
            acc[15] = fmaf(xv, w3.w, acc[15]);
        }
        __syncthreads();
    }

    if (n < N) {
        bool hpath = (jq < 2);
        float scale = hpath ? g_dinv[n] : 1.0f;   // fold dinv[src] into h1 rows
        #pragma unroll
        for (int o = 0; o < 16; o++) acc[o] *= scale;
        float* base = hpath ? &g_h1[n * JW + jq * 16]
                            : &g_r1[n * JW + (jq - 2) * 16];
        float4* d4 = (float4*)base;
        d4[0] = make_float4(acc[0],  acc[1],  acc[2],  acc[3]);
        d4[1] = make_float4(acc[4],  acc[5],  acc[6],  acc[7]);
        d4[2] = make_float4(acc[8],  acc[9],  acc[10], acc[11]);
        d4[3] = make_float4(acc[12], acc[13], acc[14], acc[15]);
    }
}

// ---------------- pull aggregation, width 32: warp per node ----------------
// agg1[n][c] = dinv[n] * sum_{s in N(n)} h1[s][c]   (h1 pre-scaled by dinv[s])
__global__ __launch_bounds__(256) void gather32_kernel(int N) {
    int warp = (blockIdx.x * blockDim.x + threadIdx.x) >> 5;
    int lane = threadIdx.x & 31;
    if (warp >= N) return;
    int beg = g_rowptr[warp], end = g_rowptr[warp + 1];
    float acc = 0.f;
    for (int i = beg; i < end; i += 32) {
        int idx = (i + lane < end) ? g_csr[i + lane] : 0;
        int m = min(32, end - i);
        for (int j = 0; j < m; j++) {
            int s = __shfl_sync(0xffffffffu, idx, j);
            acc += g_h1[s * JW + lane];          // 128B coalesced row read
        }
    }
    g_agg1[warp * JW + lane] = acc * g_dinv[warp];
}

// ---------------- pull aggregation, width 16: warp per node, 2 edges/iter --
__global__ __launch_bounds__(256) void gather16_kernel(int N) {
    int warp = (blockIdx.x * blockDim.x + threadIdx.x) >> 5;
    int lane = threadIdx.x & 31;
    if (warp >= N) return;
    int q   = lane & 15;
    int sub = lane >> 4;
    int beg = g_rowptr[warp], end = g_rowptr[warp + 1];
    float acc = 0.f;
    for (int i = beg; i < end; i += 32) {
        int idx = (i + lane < end) ? g_csr[i + lane] : 0;
        int m = min(32, end - i);
        for (int j = 0; j < m; j += 2) {
            int jj = j + sub;
            int s = __shfl_sync(0xffffffffu, idx, jj);
            if (jj < m) acc += g_hfs[s * HIDC + q];   // 2x64B per iter
        }
    }
    acc += __shfl_xor_sync(0xffffffffu, acc, 16);
    if (sub == 0) g_aggh[warp * HIDC + q] = acc * g_dinv[warp];
}

// ---------------- combine conv1: h = mean_k relu(agg + root + bias) --------
__global__ __launch_bounds__(256) void combine_kernel(
    const float* __restrict__ b1,    // [K, HID] = 32
    float* __restrict__ feat_out,
    int N, int write_feat)
{
    __shared__ float b1s[32];
    int t = threadIdx.x;
    if (t < 32) b1s[t] = b1[t];
    __syncthreads();

    int n = blockIdx.x * blockDim.x + t;
    if (n >= N) return;

    float pre[32];
    const float4* a4 = (const float4*)&g_agg1[n * JW];
    const float4* r4 = (const float4*)&g_r1 [n * JW];
    #pragma unroll
    for (int q = 0; q < 8; q++) {
        float4 av = a4[q], rv = r4[q];
        pre[q * 4 + 0] = av.x + rv.x + b1s[q * 4 + 0];
        pre[q * 4 + 1] = av.y + rv.y + b1s[q * 4 + 1];
        pre[q * 4 + 2] = av.z + rv.z + b1s[q * 4 + 2];
        pre[q * 4 + 3] = av.w + rv.w + b1s[q * 4 + 3];
    }
    float h[16];
    #pragma unroll
    for (int o = 0; o < 16; o++) {
        float a0 = fmaxf(pre[o],      0.f);
        float a1 = fmaxf(pre[16 + o], 0.f);
        h[o] = 0.5f * (a0 + a1);   // mean over K; outer relu is a no-op (>=0)
    }
    float dn = g_dinv[n];
    float4 v0 = make_float4(h[0],  h[1],  h[2],  h[3]);
    float4 v1 = make_float4(h[4],  h[5],  h[6],  h[7]);
    float4 v2 = make_float4(h[8],  h[9],  h[10], h[11]);
    float4 v3 = make_float4(h[12], h[13], h[14], h[15]);
    float4* hf4 = (float4*)&g_hf[n * HIDC];
    hf4[0] = v0; hf4[1] = v1; hf4[2] = v2; hf4[3] = v3;
    float4* hs4 = (float4*)&g_hfs[n * HIDC];
    hs4[0] = make_float4(h[0] * dn,  h[1] * dn,  h[2] * dn,  h[3] * dn);
    hs4[1] = make_float4(h[4] * dn,  h[5] * dn,  h[6] * dn,  h[7] * dn);
    hs4[2] = make_float4(h[8] * dn,  h[9] * dn,  h[10] * dn, h[11] * dn);
    hs4[3] = make_float4(h[12] * dn, h[13] * dn, h[14] * dn, h[15] * dn);
    if (write_feat) {
        float4* f4 = (float4*)&feat_out[(long long)n * CLSC];
        f4[0] = v0; f4[1] = v1; f4[2] = v2; f4[3] = v3;
    }
}

// ---------------- final: logits = (S@h)@Wi + h@Wr + b, then log_softmax ----
__global__ __launch_bounds__(256) void final_kernel(
    const float* __restrict__ iw2,   // [K, HID, C]
    const float* __restrict__ rw2,   // [K, HID, C]
    const float* __restrict__ b2,    // [K, C]
    float* __restrict__ out, int N)
{
    __shared__ float wi[16][16], wr[16][16], bs[16];
    int t = threadIdx.x;
    {
        int o = t >> 4, c = t & 15;
        wi[o][c] = 0.5f * (iw2[o * 16 + c] + iw2[256 + o * 16 + c]);
        wr[o][c] = 0.5f * (rw2[o * 16 + c] + rw2[256 + o * 16 + c]);
    }
    if (t < 16) bs[t] = 0.5f * (b2[t] + b2[16 + t]);
    __syncthreads();

    int n = blockIdx.x * blockDim.x + t;
    if (n >= N) return;

    float ah[16], hh[16];
    const float4* a4 = (const float4*)&g_aggh[n * HIDC];
    const float4* h4 = (const float4*)&g_hf [n * HIDC];
    #pragma unroll
    for (int q = 0; q < 4; q++) {
        float4 av = a4[q], hv = h4[q];
        ah[q * 4 + 0] = av.x; ah[q * 4 + 1] = av.y;
        ah[q * 4 + 2] = av.z; ah[q * 4 + 3] = av.w;
        hh[q * 4 + 0] = hv.x; hh[q * 4 + 1] = hv.y;
        hh[q * 4 + 2] = hv.z; hh[q * 4 + 3] = hv.w;
    }
    float lg[16];
    #pragma unroll
    for (int c = 0; c < 16; c++) lg[c] = bs[c];
    #pragma unroll
    for (int o = 0; o < 16; o++) {
        float a = ah[o], h = hh[o];
        #pragma unroll
        for (int c = 0; c < 16; c++)
            lg[c] = fmaf(a, wi[o][c], fmaf(h, wr[o][c], lg[c]));
    }
    float m = -1e30f;
    #pragma unroll
    for (int c = 0; c < 16; c++) m = fmaxf(m, lg[c]);
    float s = 0.f;
    #pragma unroll
    for (int c = 0; c < 16; c++) s += __expf(lg[c] - m);
    float lse = m + __logf(s);

    float4* o4 = (float4*)&out[(long long)n * CLSC];
    o4[0] = make_float4(lg[0] - lse,  lg[1] - lse,  lg[2] - lse,  lg[3] - lse);
    o4[1] = make_float4(lg[4] - lse,  lg[5] - lse,  lg[6] - lse,  lg[7] - lse);
    o4[2] = make_float4(lg[8] - lse,  lg[9] - lse,  lg[10] - lse, lg[11] - lse);
    o4[3] = make_float4(lg[12] - lse, lg[13] - lse, lg[14] - lse, lg[15] - lse);
}

// ---------------- launch ----------------
extern "C" void kernel_launch(void* const* d_in, const int* in_sizes, int n_in,
                              void* d_out, int out_size) {
    const float* x   = (const float*)d_in[0];
    const void*  ei  = d_in[1];                  // int32 or int64, detected on device
    const float* iw1 = (const float*)d_in[2];
    const float* rw1 = (const float*)d_in[3];
    const float* b1  = (const float*)d_in[4];
    const float* iw2 = (const float*)d_in[5];
    const float* rw2 = (const float*)d_in[6];
    const float* b2  = (const float*)d_in[7];
    float* out = (float*)d_out;

    int N = in_sizes[0] / F_INC;
    int E = in_sizes[1] / 2;
    if (N > NMAX) N = NMAX;
    if (E > EMAX) E = EMAX;

    int write_feat = (out_size >= 2 * N * CLSC) ? 1 : 0;
    float* feat_out = write_feat ? (out + (long long)N * CLSC) : out;

    int nb = (N + 255) / 256;                    // scan blocks (<= 1024)

    detect_kernel<<<1, 32>>>((const unsigned int*)ei);
    zeroi_kernel<<<(N + 1023) / 1024, 1024>>>(N);
    deg_kernel<<<(E + 255) / 256, 256>>>(ei, E);
    scan1_kernel<<<nb, 256>>>(N);
    scan2_kernel<<<1, 512>>>(nb);
    scan3_kernel<<<nb, 256>>>(N);
    fill_kernel<<<(E + 255) / 256, 256>>>(ei, E);
    gemm1_kernel<<<(N + 63) / 64, 256>>>(x, iw1, rw1, N);

    int gblocks = (N * 32 + 255) / 256;          // warp per node
    gather32_kernel<<<gblocks, 256>>>(N);

    combine_kernel<<<nb, 256>>>(b1, feat_out, N, write_feat);

    gather16_kernel<<<gblocks, 256>>>(N);

    final_kernel<<<nb, 256>>>(iw2, rw2, b2, out, N);
}